// round 16
// baseline (speedup 1.0000x reference)
#include <cuda_runtime.h>
#include <cuda_fp16.h>
#include <cstdint>

// LePEAttention R16: window-QUAD CTAs + vectorized STS staging.
// R15's binder was L1 again: load-phase strided LDGs (~10us) + scalar STS
// scatter (~7us). Now: 4 adjacent windows per CTA -> loader reads 32B
// contiguous per image row (4 lines/warp-LDG, was 8); Q/K/V staged with
// uint4/float4 STS (28 -> ~7 STS per thread). Per-warp compute identical to
// R15 (fp16 dual-packed QK, ex2.f16x2, ones-MMA row sums, fp16 PV).
// grid 512 = (b, wquad, h), 1024 thr: warp w computes window w>>3.

#define HW_ 16384
#define WW_ 128
#define CC_ 64

__device__ __forceinline__ uint32_t f16p(float lo_elem, float hi_elem) {
    uint32_t r; asm("cvt.rn.f16x2.f32 %0, %1, %2;" : "=r"(r) : "f"(hi_elem), "f"(lo_elem)); return r;
}
__device__ __forceinline__ uint32_t ex2h2(uint32_t s) {
    uint32_t r; asm("ex2.approx.f16x2 %0, %1;" : "=r"(r) : "r"(s)); return r;
}
__device__ __forceinline__ float f16rt(float v) { return __half2float(__float2half_rn(v)); }

#define MMAF16(c0,c1,c2,c3, a0,a1,a2,a3, b0,b1) \
    asm volatile("mma.sync.aligned.m16n8k16.row.col.f32.f16.f16.f32 " \
        "{%0,%1,%2,%3}, {%4,%5,%6,%7}, {%8,%9}, {%0,%1,%2,%3};" \
        : "+f"(c0), "+f"(c1), "+f"(c2), "+f"(c3) \
        : "r"(a0), "r"(a1), "r"(a2), "r"(a3), "r"(b0), "r"(b1))

__global__ void __launch_bounds__(1024, 1)
lepe_mma8(const float* __restrict__ temp,
          const float* __restrict__ cw,
          const float* __restrict__ cb,
          float* __restrict__ out)
{
    const int bid = blockIdx.x;        // 0..511 = (b, wq, h)
    const int h   = bid & 7;
    const int grp = bid >> 3;          // 0..63
    const int b   = grp >> 4;
    const int wq  = grp & 15;          // window quad: windows 4wq .. 4wq+3
    const int x0  = 8*wq;              // x range [x0, x0+8)

    const int tid  = threadIdx.x;      // 0..1023
    const int lane = tid & 31;
    const int w    = tid >> 5;         // 0..31
    const int g    = lane >> 2;
    const int q    = lane & 3;

    // Per-window arrays, [4] indexed by window-in-quad.
    __shared__ __align__(16) uint32_t KF[4][32][32];   // 16 KB
    __shared__ __align__(16) uint2    VF[4][16][32];   // 16 KB
    __shared__ __align__(16) uint32_t QS[4][256*8];    // 32 KB
    __shared__ __align__(16) float    vS[4][262*8];    // 33.5 KB
    __shared__ float wS[72];
    __shared__ float bS[8];

    if (tid < 96) {
        const int wi = tid / 24, r = tid % 24;
        vS[wi][r] = 0.f; vS[wi][262*8 - 24 + r] = 0.f;
    }
    if (tid < 72) wS[tid] = cw[(h*8 + (tid & 7))*9 + (tid >> 3)];   // wS[tap*8+d]
    if (tid < 8)  bS[tid] = cb[h*8 + tid];

    const float qscale = 0.35355339059327373f * 1.44269504088896340736f; // 8^-0.5 * log2(e)

    // ---- joint coalesced load: thread -> (ly = tid>>3, xl = tid&7) ----
    // xl covers 32 contiguous bytes per row spanning all 4 windows.
    const int ly  = tid >> 3;          // image row 0..127
    const int xl  = tid & 7;
    const int wi0 = xl >> 1;           // window this value belongs to
    const int tok = ly*2 + (xl & 1);   // token within that window
    const size_t gbase = (size_t)ly*WW_ + (x0 + xl);

    // Q: fp16 hi/lo packed pairs, 2x STS.128
    {
        const float* qg = temp + ((size_t)(b*3 + 0)*CC_ + h*8)*HW_ + gbase;
        float v[8], hi[8];
        #pragma unroll
        for (int d = 0; d < 8; d++) {
            v[d]  = qg[(size_t)d*HW_] * qscale;
            hi[d] = f16rt(v[d]);
        }
        uint4 qh = make_uint4(f16p(hi[0],hi[1]), f16p(hi[2],hi[3]),
                              f16p(hi[4],hi[5]), f16p(hi[6],hi[7]));
        uint4 ql = make_uint4(f16p(v[0]-hi[0], v[1]-hi[1]), f16p(v[2]-hi[2], v[3]-hi[3]),
                              f16p(v[4]-hi[4], v[5]-hi[5]), f16p(v[6]-hi[6], v[7]-hi[7]));
        *(uint4*)&QS[wi0][tok*8]     = qh;
        *(uint4*)&QS[wi0][tok*8 + 4] = ql;
    }
    // K: fp16 fragment-order, 1x STS.128
    {
        const float* kg = temp + ((size_t)(b*3 + 1)*CC_ + h*8)*HW_ + gbase;
        float kv[8];
        #pragma unroll
        for (int d = 0; d < 8; d++) kv[d] = kg[(size_t)d*HW_];
        const int t = tok >> 3, gg = tok & 7;
        uint4 kf4 = make_uint4(f16p(kv[0],kv[1]), f16p(kv[2],kv[3]),
                               f16p(kv[4],kv[5]), f16p(kv[6],kv[7]));
        *(uint4*)&KF[wi0][t][gg*4] = kf4;
    }
    // V exact, 2x STS.128
    {
        const float* vg = temp + ((size_t)(b*3 + 2)*CC_ + h*8)*HW_ + gbase;
        float v[8];
        #pragma unroll
        for (int d = 0; d < 8; d++) v[d] = vg[(size_t)d*HW_];
        *(float4*)&vS[wi0][(tok + 3)*8]     = make_float4(v[0], v[1], v[2], v[3]);
        *(float4*)&vS[wi0][(tok + 3)*8 + 4] = make_float4(v[4], v[5], v[6], v[7]);
    }
    __syncthreads();

    // ---- V fp16 fragment packing: threads 0-511, 128 per window ----
    if (tid < 512) {
        const int wi = tid >> 7;
        const int u  = tid & 127;
        const int c = u >> 3, p = u & 7;
        const float* v0 = &vS[wi][(2*u + 3)*8];
        const float* v1 = &vS[wi][(2*u + 4)*8];
        uint32_t* VFu = (uint32_t*)&VF[wi][0][0];
        #pragma unroll
        for (int d = 0; d < 8; d++) {
            uint32_t pk = f16p(v0[d], v1[d]);
            int lane_t = d*4 + (p & 3);
            int fld    = (p < 4) ? 0 : 1;
            VFu[(c*32 + lane_t)*2 + fld] = pk;
        }
    }
    __syncthreads();

    // ---- compute: warp w -> window w>>3 ----
    const int wi = w >> 3;
    const int wl = w & 7;
    const uint32_t* QSw = QS[wi];
    const float*    vSw = vS[wi];

    const int R0 = wl*32, R1 = wl*32 + 16;
    const uint32_t aA0 = QSw[(R0 + g    )*8 + q];
    const uint32_t aA1 = QSw[(R0 + g + 8)*8 + q];
    const uint32_t aA2 = QSw[(R0 + g    )*8 + 4 + q];
    const uint32_t aA3 = QSw[(R0 + g + 8)*8 + 4 + q];
    const uint32_t aB0 = QSw[(R1 + g    )*8 + q];
    const uint32_t aB1 = QSw[(R1 + g + 8)*8 + q];
    const uint32_t aB2 = QSw[(R1 + g    )*8 + 4 + q];
    const uint32_t aB3 = QSw[(R1 + g + 8)*8 + 4 + q];
    const uint32_t ONES = 0x3C003C00u;   // fp16x2 (1.0, 1.0)

    float mA0=0.f,mA1=0.f,mA2=0.f,mA3=0.f;
    float mB0=0.f,mB1=0.f,mB2=0.f,mB3=0.f;
    float rA0=0.f,rA1=0.f,rA2=0.f,rA3=0.f;
    float rB0=0.f,rB1=0.f,rB2=0.f,rB3=0.f;

    #pragma unroll 2
    for (int c16 = 0; c16 < 16; c16++) {
        uint32_t pvA[4], pvB[4];
        #pragma unroll
        for (int sub = 0; sub < 2; sub++) {
            const uint32_t kf = KF[wi][2*c16 + sub][lane];
            {
                float s0=0.f,s1=0.f,s2=0.f,s3=0.f;
                MMAF16(s0,s1,s2,s3, aA0,aA1,aA2,aA3, kf, kf);
                pvA[2*sub]   = ex2h2(f16p(s0, s1));
                pvA[2*sub+1] = ex2h2(f16p(s2, s3));
            }
            {
                float s0=0.f,s1=0.f,s2=0.f,s3=0.f;
                MMAF16(s0,s1,s2,s3, aB0,aB1,aB2,aB3, kf, kf);
                pvB[2*sub]   = ex2h2(f16p(s0, s1));
                pvB[2*sub+1] = ex2h2(f16p(s2, s3));
            }
        }
        const uint2 vf = VF[wi][c16][lane];
        MMAF16(mA0,mA1,mA2,mA3, pvA[0],pvA[1],pvA[2],pvA[3], vf.x, vf.y);
        MMAF16(rA0,rA1,rA2,rA3, pvA[0],pvA[1],pvA[2],pvA[3], ONES, ONES);
        MMAF16(mB0,mB1,mB2,mB3, pvB[0],pvB[1],pvB[2],pvB[3], vf.x, vf.y);
        MMAF16(rB0,rB1,rB2,rB3, pvB[0],pvB[1],pvB[2],pvB[3], ONES, ONES);
    }

    // ---- epilogue: lane owns 4 rows x (d = 2q, 2q+1) ----
    float2 wp9[9];
    #pragma unroll
    for (int tap = 0; tap < 9; tap++) wp9[tap] = *(const float2*)&wS[tap*8 + 2*q];
    const float2 bias = *(const float2*)&bS[2*q];

    const float oc[4][2] = {
        { mA0 / rA0, mA1 / rA0 },
        { mA2 / rA2, mA3 / rA2 },
        { mB0 / rB0, mB1 / rB0 },
        { mB2 / rB2, mB3 / rB2 },
    };
    const int rows[4] = { R0 + g, R0 + g + 8, R1 + g, R1 + g + 8 };
    const int xw = x0 + wi*2;          // x base of this warp's window

    #pragma unroll
    for (int ri = 0; ri < 4; ri++) {
        const int tk = rows[ri];
        const int y  = tk >> 1;
        const int xi = tk & 1;
        float rx = bias.x, ry = bias.y;
        #pragma unroll
        for (int ky = 0; ky < 3; ky++) {
            #pragma unroll
            for (int kx = 0; kx < 3; kx++) {
                int dxi = xi + kx - 1;
                if (dxi >= 0 && dxi <= 1) {
                    int ptok = tk + (ky - 1)*2 + (kx - 1) + 3;
                    float2 v = *(const float2*)&vSw[ptok*8 + 2*q];
                    float2 wv = wp9[ky*3 + kx];
                    rx += v.x * wv.x;
                    ry += v.y * wv.y;
                }
            }
        }
        const size_t obase = ((size_t)b*HW_ + (size_t)y*WW_ + xw + xi)*CC_ + h*8 + 2*q;
        *(float2*)(out + obase) = make_float2(oc[ri][0] + rx, oc[ri][1] + ry);
    }
}

extern "C" void kernel_launch(void* const* d_in, const int* in_sizes, int n_in,
                              void* d_out, int out_size)
{
    const float* temp = (const float*)d_in[0];
    const float* cw   = (const float*)d_in[1];
    const float* cb   = (const float*)d_in[2];
    float* out        = (float*)d_out;
    lepe_mma8<<<512, 1024>>>(temp, cw, cb, out);
}

// round 17
// speedup vs baseline: 1.2673x; 1.2673x over previous
#include <cuda_runtime.h>
#include <cuda_fp16.h>
#include <cstdint>

// LePEAttention R17: R15 launch shape (grid 1024, 512 thr, 2 CTAs/SM,
// window-PAIR CTAs) + R16's vectorized STS staging (20 scalar STS.32 -> 5
// STS.128 per loader thread). R16's window-quad 1024-thr/1-CTA-per-SM shape
// lost 10us to wave quantization + unshielded __syncthreads despite lower L1;
// this keeps only the part of R16 that helped.
// Compute per warp identical to R15: fp16 dual-packed QK m16n8k16,
// ex2.approx.f16x2 softmax, ones-MMA row sums, fp16 PV. rel_err must stay
// bit-identical 2.517e-4.

#define HW_ 16384
#define WW_ 128
#define CC_ 64

__device__ __forceinline__ uint32_t f16p(float lo_elem, float hi_elem) {
    uint32_t r; asm("cvt.rn.f16x2.f32 %0, %1, %2;" : "=r"(r) : "f"(hi_elem), "f"(lo_elem)); return r;
}
__device__ __forceinline__ uint32_t ex2h2(uint32_t s) {
    uint32_t r; asm("ex2.approx.f16x2 %0, %1;" : "=r"(r) : "r"(s)); return r;
}
__device__ __forceinline__ float f16rt(float v) { return __half2float(__float2half_rn(v)); }

#define MMAF16(c0,c1,c2,c3, a0,a1,a2,a3, b0,b1) \
    asm volatile("mma.sync.aligned.m16n8k16.row.col.f32.f16.f16.f32 " \
        "{%0,%1,%2,%3}, {%4,%5,%6,%7}, {%8,%9}, {%0,%1,%2,%3};" \
        : "+f"(c0), "+f"(c1), "+f"(c2), "+f"(c3) \
        : "r"(a0), "r"(a1), "r"(a2), "r"(a3), "r"(b0), "r"(b1))

__global__ void __launch_bounds__(512, 2)
lepe_mma9(const float* __restrict__ temp,
          const float* __restrict__ cw,
          const float* __restrict__ cb,
          float* __restrict__ out)
{
    const int bid = blockIdx.x;        // 0..1023 = (b, wp, h)
    const int h   = bid & 7;
    const int grp = bid >> 3;
    const int b   = grp >> 5;
    const int wp  = grp & 31;          // window pair: windows 2wp, 2wp+1
    const int x0  = 4*wp;

    const int tid  = threadIdx.x;      // 0..511
    const int lane = tid & 31;
    const int w    = tid >> 5;         // 0..15
    const int g    = lane >> 2;
    const int q    = lane & 3;

    __shared__ __align__(16) uint32_t KF[2][32][32];   // 8 KB
    __shared__ __align__(16) uint2    VF[2][16][32];   // 8 KB
    __shared__ __align__(16) uint32_t QS[2][256*8];    // 16 KB
    __shared__ __align__(16) float    vS[2][262*8];    // 16.8 KB
    __shared__ float wS[72];
    __shared__ float bS[8];

    if (tid < 48) {
        const int wi = tid / 24, r = tid % 24;
        vS[wi][r] = 0.f; vS[wi][262*8 - 24 + r] = 0.f;
    }
    if (tid < 72) wS[tid] = cw[(h*8 + (tid & 7))*9 + (tid >> 3)];   // wS[tap*8+d]
    if (tid < 8)  bS[tid] = cb[h*8 + tid];

    const float qscale = 0.35355339059327373f * 1.44269504088896340736f; // 8^-0.5 * log2(e)

    // ---- joint coalesced load: thread -> (ly = tid>>2, xl = tid&3) ----
    const int ly  = tid >> 2;
    const int xl  = tid & 3;
    const int wi0 = xl >> 1;
    const int tok = ly*2 + (xl & 1);
    const size_t gbase = (size_t)ly*WW_ + (x0 + xl);

    // Q: fp16 hi/lo packed pairs, 2x STS.128
    {
        const float* qg = temp + ((size_t)(b*3 + 0)*CC_ + h*8)*HW_ + gbase;
        float v[8], hi[8];
        #pragma unroll
        for (int d = 0; d < 8; d++) {
            v[d]  = qg[(size_t)d*HW_] * qscale;
            hi[d] = f16rt(v[d]);
        }
        uint4 qh = make_uint4(f16p(hi[0],hi[1]), f16p(hi[2],hi[3]),
                              f16p(hi[4],hi[5]), f16p(hi[6],hi[7]));
        uint4 ql = make_uint4(f16p(v[0]-hi[0], v[1]-hi[1]), f16p(v[2]-hi[2], v[3]-hi[3]),
                              f16p(v[4]-hi[4], v[5]-hi[5]), f16p(v[6]-hi[6], v[7]-hi[7]));
        *(uint4*)&QS[wi0][tok*8]     = qh;
        *(uint4*)&QS[wi0][tok*8 + 4] = ql;
    }
    // K: fp16 fragment-order, 1x STS.128
    {
        const float* kg = temp + ((size_t)(b*3 + 1)*CC_ + h*8)*HW_ + gbase;
        float kv[8];
        #pragma unroll
        for (int d = 0; d < 8; d++) kv[d] = kg[(size_t)d*HW_];
        const int t = tok >> 3, gg = tok & 7;
        uint4 kf4 = make_uint4(f16p(kv[0],kv[1]), f16p(kv[2],kv[3]),
                               f16p(kv[4],kv[5]), f16p(kv[6],kv[7]));
        *(uint4*)&KF[wi0][t][gg*4] = kf4;
    }
    // V exact, 2x STS.128
    {
        const float* vg = temp + ((size_t)(b*3 + 2)*CC_ + h*8)*HW_ + gbase;
        float v[8];
        #pragma unroll
        for (int d = 0; d < 8; d++) v[d] = vg[(size_t)d*HW_];
        *(float4*)&vS[wi0][(tok + 3)*8]     = make_float4(v[0], v[1], v[2], v[3]);
        *(float4*)&vS[wi0][(tok + 3)*8 + 4] = make_float4(v[4], v[5], v[6], v[7]);
    }
    __syncthreads();

    // ---- V fp16 fragment packing: threads 0-255, 128 per window ----
    if (tid < 256) {
        const int wi = tid >> 7;
        const int u  = tid & 127;
        const int c = u >> 3, p = u & 7;
        const float* v0 = &vS[wi][(2*u + 3)*8];
        const float* v1 = &vS[wi][(2*u + 4)*8];
        uint32_t* VFu = (uint32_t*)&VF[wi][0][0];
        #pragma unroll
        for (int d = 0; d < 8; d++) {
            uint32_t pk = f16p(v0[d], v1[d]);
            int lane_t = d*4 + (p & 3);
            int fld    = (p < 4) ? 0 : 1;
            VFu[(c*32 + lane_t)*2 + fld] = pk;
        }
    }
    __syncthreads();

    // ---- compute: warps 0-7 -> window 0, warps 8-15 -> window 1 ----
    const int wi = w >> 3;
    const int wl = w & 7;
    const uint32_t* QSw = QS[wi];
    const float*    vSw = vS[wi];

    const int R0 = wl*32, R1 = wl*32 + 16;
    const uint32_t aA0 = QSw[(R0 + g    )*8 + q];
    const uint32_t aA1 = QSw[(R0 + g + 8)*8 + q];
    const uint32_t aA2 = QSw[(R0 + g    )*8 + 4 + q];
    const uint32_t aA3 = QSw[(R0 + g + 8)*8 + 4 + q];
    const uint32_t aB0 = QSw[(R1 + g    )*8 + q];
    const uint32_t aB1 = QSw[(R1 + g + 8)*8 + q];
    const uint32_t aB2 = QSw[(R1 + g    )*8 + 4 + q];
    const uint32_t aB3 = QSw[(R1 + g + 8)*8 + 4 + q];
    const uint32_t ONES = 0x3C003C00u;   // fp16x2 (1.0, 1.0)

    float mA0=0.f,mA1=0.f,mA2=0.f,mA3=0.f;
    float mB0=0.f,mB1=0.f,mB2=0.f,mB3=0.f;
    float rA0=0.f,rA1=0.f,rA2=0.f,rA3=0.f;
    float rB0=0.f,rB1=0.f,rB2=0.f,rB3=0.f;

    #pragma unroll 2
    for (int c16 = 0; c16 < 16; c16++) {
        uint32_t pvA[4], pvB[4];
        #pragma unroll
        for (int sub = 0; sub < 2; sub++) {
            const uint32_t kf = KF[wi][2*c16 + sub][lane];
            {
                float s0=0.f,s1=0.f,s2=0.f,s3=0.f;
                MMAF16(s0,s1,s2,s3, aA0,aA1,aA2,aA3, kf, kf);
                pvA[2*sub]   = ex2h2(f16p(s0, s1));
                pvA[2*sub+1] = ex2h2(f16p(s2, s3));
            }
            {
                float s0=0.f,s1=0.f,s2=0.f,s3=0.f;
                MMAF16(s0,s1,s2,s3, aB0,aB1,aB2,aB3, kf, kf);
                pvB[2*sub]   = ex2h2(f16p(s0, s1));
                pvB[2*sub+1] = ex2h2(f16p(s2, s3));
            }
        }
        const uint2 vf = VF[wi][c16][lane];
        MMAF16(mA0,mA1,mA2,mA3, pvA[0],pvA[1],pvA[2],pvA[3], vf.x, vf.y);
        MMAF16(rA0,rA1,rA2,rA3, pvA[0],pvA[1],pvA[2],pvA[3], ONES, ONES);
        MMAF16(mB0,mB1,mB2,mB3, pvB[0],pvB[1],pvB[2],pvB[3], vf.x, vf.y);
        MMAF16(rB0,rB1,rB2,rB3, pvB[0],pvB[1],pvB[2],pvB[3], ONES, ONES);
    }

    // ---- epilogue: lane owns 4 rows x (d = 2q, 2q+1) ----
    float2 wp9[9];
    #pragma unroll
    for (int tap = 0; tap < 9; tap++) wp9[tap] = *(const float2*)&wS[tap*8 + 2*q];
    const float2 bias = *(const float2*)&bS[2*q];

    const float oc[4][2] = {
        { mA0 / rA0, mA1 / rA0 },
        { mA2 / rA2, mA3 / rA2 },
        { mB0 / rB0, mB1 / rB0 },
        { mB2 / rB2, mB3 / rB2 },
    };
    const int rows[4] = { R0 + g, R0 + g + 8, R1 + g, R1 + g + 8 };
    const int xw = x0 + wi*2;

    #pragma unroll
    for (int ri = 0; ri < 4; ri++) {
        const int tk = rows[ri];
        const int y  = tk >> 1;
        const int xi = tk & 1;
        float rx = bias.x, ry = bias.y;
        #pragma unroll
        for (int ky = 0; ky < 3; ky++) {
            #pragma unroll
            for (int kx = 0; kx < 3; kx++) {
                int dxi = xi + kx - 1;
                if (dxi >= 0 && dxi <= 1) {
                    int ptok = tk + (ky - 1)*2 + (kx - 1) + 3;
                    float2 v = *(const float2*)&vSw[ptok*8 + 2*q];
                    float2 wv = wp9[ky*3 + kx];
                    rx += v.x * wv.x;
                    ry += v.y * wv.y;
                }
            }
        }
        const size_t obase = ((size_t)b*HW_ + (size_t)y*WW_ + xw + xi)*CC_ + h*8 + 2*q;
        *(float2*)(out + obase) = make_float2(oc[ri][0] + rx, oc[ri][1] + ry);
    }
}

extern "C" void kernel_launch(void* const* d_in, const int* in_sizes, int n_in,
                              void* d_out, int out_size)
{
    const float* temp = (const float*)d_in[0];
    const float* cw   = (const float*)d_in[1];
    const float* cb   = (const float*)d_in[2];
    float* out        = (float*)d_out;
    lepe_mma9<<<1024, 512>>>(temp, cw, cb, out);
}